// round 15
// baseline (speedup 1.0000x reference)
#include <cuda_runtime.h>
#include <cuda_fp16.h>
#include <math.h>
#include <stdint.h>

#define FDIM 256
#define TOUT 8
#define N_MONO 150000
#define N_CLEAV 100000
#define N_FRAG 80000
#define N_OUTN 40000

// ---- scratch (device globals: allocation-free rule) ----
__device__ __half g_feat_h[(size_t)N_MONO * FDIM];         // half feature table (77MB)
__device__ __half g_cleav_h[(size_t)N_CLEAV * 2 * FDIM];   // [100000, 512] half
__device__ float  g_c1[(size_t)N_FRAG * FDIM];             // [80000, 256]
__device__ __half g_h1h[(size_t)N_FRAG * FDIM];            // h1 (half)
__device__ __half g_h2h[(size_t)N_FRAG * FDIM];            // h2 (half)
__device__ float  g_fragout[(size_t)N_FRAG * TOUT];
__device__ __half g_Wcat_h[1024 * 768];                    // interleaved [Wih|Whh]
__device__ float  g_bias[1024];                            // interleaved b_ih+b_hh

__device__ __forceinline__ float warp_sum(float v) {
#pragma unroll
    for (int o = 16; o; o >>= 1) v += __shfl_xor_sync(0xffffffffu, v, o);
    return v;
}
__device__ __forceinline__ float sigf(float x) { return 1.0f / (1.0f + expf(-x)); }

__device__ __forceinline__ uint32_t smem_u32(const void* p) {
    uint32_t a;
    asm("{ .reg .u64 t; cvta.to.shared.u64 t, %1; cvt.u32.u64 %0, t; }" : "=r"(a) : "l"(p));
    return a;
}
__device__ __forceinline__ void ldmx4(uint32_t* r, uint32_t addr) {
    asm volatile("ldmatrix.sync.aligned.m8n8.x4.shared.b16 {%0,%1,%2,%3}, [%4];"
        : "=r"(r[0]), "=r"(r[1]), "=r"(r[2]), "=r"(r[3]) : "r"(addr));
}
__device__ __forceinline__ void mma_f16(float* d, const uint32_t* a, const uint32_t* b) {
    asm volatile(
        "mma.sync.aligned.m16n8k16.row.col.f32.f16.f16.f32 "
        "{%0,%1,%2,%3}, {%4,%5,%6,%7}, {%8,%9}, {%0,%1,%2,%3};"
        : "+f"(d[0]), "+f"(d[1]), "+f"(d[2]), "+f"(d[3])
        : "r"(a[0]), "r"(a[1]), "r"(a[2]), "r"(a[3]), "r"(b[0]), "r"(b[1]));
}
#define CP_ASYNC16(dst, src) \
    asm volatile("cp.async.cg.shared.global [%0], [%1], 16;" :: "r"(dst), "l"(src))
#define CP_COMMIT() asm volatile("cp.async.commit_group;" ::: "memory")
#define CP_WAIT(n)  asm volatile("cp.async.wait_group %0;" :: "n"(n) : "memory")

// ============================================================
// K-1: convert feature fp32 -> half table (4 elems/thread)
// ============================================================
__global__ __launch_bounds__(256) void conv_feat(const float* __restrict__ feature)
{
    size_t i = ((size_t)blockIdx.x * 256 + threadIdx.x) * 4;
    float4 v = *(const float4*)(feature + i);
    __half2 h0 = __floats2half2_rn(v.x, v.y);
    __half2 h1 = __floats2half2_rn(v.z, v.w);
    *(uint2*)(g_feat_h + i) = make_uint2(
        *(const uint32_t*)&h0, *(const uint32_t*)&h1);
}

// ============================================================
// K0: build interleaved half weights + combined bias.
// Output col' = 4h + q, q: 0=i, 1=g, 2=f, 3=o (orig gate row blocks i,f,g,o).
// ============================================================
__global__ __launch_bounds__(256) void conv_w(
    const float* __restrict__ Wih, const float* __restrict__ Whh,
    const float* __restrict__ bih, const float* __restrict__ bhh)
{
    int idx = blockIdx.x * 256 + threadIdx.x;
    if (idx >= 1024 * 768) return;
    int rp = idx / 768, k = idx % 768;
    int h = rp >> 2, q = rp & 3;
    int orig = (q == 0) ? h : (q == 1) ? 512 + h : (q == 2) ? 256 + h : 768 + h;
    float v = (k < 512) ? Wih[orig * 512 + k] : Whh[orig * 256 + (k - 512)];
    g_Wcat_h[idx] = __float2half_rn(v);
    if (k == 0) g_bias[rp] = bih[orig] + bhh[orig];
}

// ============================================================
// K1: cleavage attention, ONE WARP PER NODE (8 nodes/block).
// Lane owns dims [8*lane, 8*lane+8): one uint4 (8 halfs) load per
// gathered row, 8 warp_sum logits, softmax, uint4 half stores.
// ============================================================
__global__ __launch_bounds__(256) void cleav_kernel(
    const float* __restrict__ WgL,
    const float* __restrict__ WgR,
    const int* __restrict__ lost_src,
    const int* __restrict__ ret_src)
{
    int w = threadIdx.x >> 5, lane = threadIdx.x & 31;
    int i = blockIdx.x * 8 + w;

    int idx = 0;
    if (lane < 4)      idx = lost_src[i * 4 + lane];
    else if (lane < 8) idx = ret_src[i * 4 + (lane - 4)];
    int rows[8];
#pragma unroll
    for (int r = 0; r < 8; r++) rows[r] = __shfl_sync(0xffffffffu, idx, r);

    int d0 = lane * 8;
    float4 la = *(const float4*)(WgL + d0);
    float4 lb = *(const float4*)(WgL + d0 + 4);
    float4 ra = *(const float4*)(WgR + d0);
    float4 rb = *(const float4*)(WgR + d0 + 4);
    float wgl[8] = {la.x, la.y, la.z, la.w, lb.x, lb.y, lb.z, lb.w};
    float wgr[8] = {ra.x, ra.y, ra.z, ra.w, rb.x, rb.y, rb.z, rb.w};

    uint4 rv[8];
    float lg[8];
#pragma unroll
    for (int r = 0; r < 8; r++) {
        rv[r] = *(const uint4*)(g_feat_h + (size_t)rows[r] * FDIM + d0);
        const __half* hp = (const __half*)&rv[r];
        float p = 0.f;
#pragma unroll
        for (int j = 0; j < 8; j++)
            p = fmaf(__half2float(hp[j]), (r < 4) ? wgl[j] : wgr[j], p);
        lg[r] = warp_sum(p);
    }

    {
        float m = fmaxf(fmaxf(lg[0], lg[1]), fmaxf(lg[2], lg[3]));
        float e0 = expf(lg[0] - m), e1 = expf(lg[1] - m);
        float e2 = expf(lg[2] - m), e3 = expf(lg[3] - m);
        float inv = 1.0f / (e0 + e1 + e2 + e3);
        e0 *= inv; e1 *= inv; e2 *= inv; e3 *= inv;
        const __half* h0 = (const __half*)&rv[0];
        const __half* h1 = (const __half*)&rv[1];
        const __half* h2 = (const __half*)&rv[2];
        const __half* h3 = (const __half*)&rv[3];
        __half ov[8];
#pragma unroll
        for (int j = 0; j < 8; j++) {
            float s = e0 * __half2float(h0[j]) + e1 * __half2float(h1[j])
                    + e2 * __half2float(h2[j]) + e3 * __half2float(h3[j]);
            ov[j] = __float2half_rn(s);
        }
        *(uint4*)(g_cleav_h + (size_t)i * 2 * FDIM + d0) = *(const uint4*)ov;
    }
    {
        float m = fmaxf(fmaxf(lg[4], lg[5]), fmaxf(lg[6], lg[7]));
        float e0 = expf(lg[4] - m), e1 = expf(lg[5] - m);
        float e2 = expf(lg[6] - m), e3 = expf(lg[7] - m);
        float inv = 1.0f / (e0 + e1 + e2 + e3);
        e0 *= inv; e1 *= inv; e2 *= inv; e3 *= inv;
        const __half* h0 = (const __half*)&rv[4];
        const __half* h1 = (const __half*)&rv[5];
        const __half* h2 = (const __half*)&rv[6];
        const __half* h3 = (const __half*)&rv[7];
        __half ov[8];
#pragma unroll
        for (int j = 0; j < 8; j++) {
            float s = e0 * __half2float(h0[j]) + e1 * __half2float(h1[j])
                    + e2 * __half2float(h2[j]) + e3 * __half2float(h3[j]);
            ov[j] = __float2half_rn(s);
        }
        *(uint4*)(g_cleav_h + (size_t)i * 2 * FDIM + FDIM + d0) = *(const uint4*)ov;
    }
}

// ============================================================
// Fused fp16 GEMM + LSTM-step epilogue.
// R8 pipeline geometry (4-slot ring, 3-stage lookahead, wait_group(2))
// — best measured GEMM-B — plus validated fixes: sentinel tail commits
// (R9) and one barrier per stage (R11). Mainloop unrolled by 4 (ring
// period): slot arithmetic constant-folds, code stays I-cache-resident.
// MODE 0: gates0 = cleav[join even] @ Wcat[:, :512]^T + bias  -> step0 -> c1,h1h
// MODE 1: gates1 = [cleav[join odd] | h1h] @ Wcat^T + bias    -> step1 -> h2h
// BM=128, BN=64, BK=32, 256 threads (8 warps, 4x2), warp tile 32x32.
// Dynamic smem: A slots 4x8KB at [0,32768), B slots 4x4KB at [32768,49152).
// ============================================================
template <int MODE>
__global__ __launch_bounds__(256, 3) void gemm_fused(const int* __restrict__ join)
{
    constexpr int K = (MODE == 0) ? 512 : 768;
    constexpr int NS = K >> 5;      // 16 / 24, both divisible by 4

    extern __shared__ __align__(16) char dsm[];
    __shared__ int sidx[128];

    int tid = threadIdx.x;
    int bm = blockIdx.y * 128;
    int bn = blockIdx.x * 64;

    if (tid < 128) sidx[tid] = join[2 * (bm + tid) + MODE];
    __syncthreads();

    // A load mapping: 128 rows x 64B, 2 chunks/thread
    int lr = tid >> 1, lh = tid & 1;
    const __half* arow_c = g_cleav_h + (size_t)sidx[lr] * 512;
    const __half* arow_h = g_h1h + (size_t)(bm + lr) * 256 - 512;  // valid for k0>=512
    int swa = (lr >> 1) & 3;
    uint32_t stA0 = lr * 64 + (((2 * lh)     ^ swa) << 4);
    uint32_t stA1 = lr * 64 + (((2 * lh + 1) ^ swa) << 4);

    // B load mapping: 64 rows x 64B, 1 chunk/thread
    int rb = tid >> 2, cb = tid & 3;
    const __half* browB = g_Wcat_h + (size_t)(bn + rb) * 768;
    uint32_t stB = rb * 64 + ((cb ^ ((rb >> 1) & 3)) << 4);

    uint32_t a_sb = smem_u32(dsm);

    int w = tid >> 5, lane = tid & 31;
    int wm = w & 3, wn = w >> 2;
    uint32_t a_addr[2], b_addr[2];
#pragma unroll
    for (int mt = 0; mt < 2; mt++) {
        int row = wm * 32 + mt * 16 + (lane & 7) + 8 * ((lane >> 3) & 1);
        int jj = (lane >> 4) & 1;
        a_addr[mt] = row * 64 + ((jj ^ ((row >> 1) & 3)) << 4);
    }
#pragma unroll
    for (int p = 0; p < 2; p++) {
        int row = wn * 32 + p * 16 + (lane & 7) + 8 * ((lane >> 4) & 1);
        int jj = (lane >> 3) & 1;
        b_addr[p] = row * 64 + ((jj ^ ((row >> 1) & 3)) << 4);
    }

    float acc[2][4][4];
#pragma unroll
    for (int mt = 0; mt < 2; mt++)
#pragma unroll
        for (int nt = 0; nt < 4; nt++)
#pragma unroll
            for (int q = 0; q < 4; q++) acc[mt][nt][q] = 0.f;

#define ISSUE_STAGE(S) do {                                                   \
        int _k0 = (S) << 5;                                                   \
        const __half* _as = (MODE == 0 || _k0 < 512) ? (arow_c + _k0)         \
                                                     : (arow_h + _k0);        \
        uint32_t _ab = a_sb + (uint32_t)((S) & 3) * 8192;                     \
        uint32_t _bb = a_sb + 32768 + (uint32_t)((S) & 3) * 4096;             \
        CP_ASYNC16(_ab + stA0, _as + 16 * lh);                                \
        CP_ASYNC16(_ab + stA1, _as + 16 * lh + 8);                            \
        CP_ASYNC16(_bb + stB, browB + _k0 + cb * 8);                          \
        CP_COMMIT();                                                          \
    } while (0)

    ISSUE_STAGE(0);
    ISSUE_STAGE(1);
    ISSUE_STAGE(2);

#pragma unroll 4
    for (int s = 0; s < NS; s++) {
        CP_WAIT(2);           // group s certified (in-order + sentinels, R9)
        __syncthreads();      // all warps finished compute s-1; stage s visible
        if (s + 3 < NS) {
            ISSUE_STAGE(s + 3);
        } else {
            CP_COMMIT();      // sentinel: keeps wait_group(2) accounting exact
        }

        uint32_t abase = a_sb + (uint32_t)(s & 3) * 8192;
        uint32_t bbase = a_sb + 32768 + (uint32_t)(s & 3) * 4096;
#pragma unroll
        for (int kk = 0; kk < 2; kk++) {
            uint32_t koff = kk << 5;
            uint32_t af[2][4];
            ldmx4(af[0], abase + (a_addr[0] ^ koff));
            ldmx4(af[1], abase + (a_addr[1] ^ koff));
            uint32_t bf[2][4];
            ldmx4(bf[0], bbase + (b_addr[0] ^ koff));
            ldmx4(bf[1], bbase + (b_addr[1] ^ koff));
#pragma unroll
            for (int mt = 0; mt < 2; mt++)
#pragma unroll
                for (int p = 0; p < 2; p++) {
                    mma_f16(acc[mt][2 * p],     af[mt], &bf[p][0]);
                    mma_f16(acc[mt][2 * p + 1], af[mt], &bf[p][2]);
                }
        }
        // single barrier per stage (WAR-safe: validated R11)
    }
    CP_WAIT(0);
    __syncthreads();
#undef ISSUE_STAGE

    // ================= fused LSTM epilogue =================
    float*  stage1 = (float*)dsm;                 // c1 tile [128][16] fp32
    __half* stage3 = (__half*)(dsm + 8192);       // h1h or h2h tile [128][16]

    int f0 = bm, h0 = bn >> 2;

    if (MODE == 1) {
        for (int i = tid; i < 512; i += 256) {
            int row = i >> 2, ch = i & 3;
            ((uint4*)stage1)[i] =
                *(const uint4*)(g_c1 + (size_t)(f0 + row) * 256 + h0 + ch * 4);
        }
        __syncthreads();
    }

    int g = lane >> 2, c = lane & 3;
#pragma unroll
    for (int mt = 0; mt < 2; mt++) {
#pragma unroll
        for (int nt = 0; nt < 4; nt++) {
            int col = bn + wn * 32 + nt * 8 + 2 * c;
            float bv0 = __ldg(g_bias + col);
            float bv1 = __ldg(g_bias + col + 1);
            float x0 = acc[mt][nt][0] + bv0;   // even c: i(r0); odd c: f(r0)
            float x1 = acc[mt][nt][1] + bv1;   // even c: g(r0); odd c: o(r0)
            float x2 = acc[mt][nt][2] + bv0;   // row r1
            float x3 = acc[mt][nt][3] + bv1;
            float a0 = sigf(x0) * tanhf(x1);   // meaningful on even-c lanes
            float a1 = sigf(x2) * tanhf(x3);
            float b0 = __shfl_xor_sync(0xffffffffu, a0, 1);
            float b1 = __shfl_xor_sync(0xffffffffu, a1, 1);
            if (c & 1) {
                int hl = wn * 8 + nt * 2 + (c >> 1);
                int rl = wm * 32 + mt * 16 + g;
                if (MODE == 0) {
                    float h1a = sigf(x1) * tanhf(b0);
                    float h1b = sigf(x3) * tanhf(b1);
                    stage1[rl * 16 + hl] = b0;
                    stage1[(rl + 8) * 16 + hl] = b1;
                    stage3[rl * 16 + hl] = __float2half_rn(h1a);
                    stage3[(rl + 8) * 16 + hl] = __float2half_rn(h1b);
                } else {
                    float c1a = stage1[rl * 16 + hl];
                    float c1b = stage1[(rl + 8) * 16 + hl];
                    float c2a = sigf(x0) * c1a + b0;
                    float c2b = sigf(x2) * c1b + b1;
                    stage3[rl * 16 + hl] = __float2half_rn(sigf(x1) * tanhf(c2a));
                    stage3[(rl + 8) * 16 + hl] = __float2half_rn(sigf(x3) * tanhf(c2b));
                }
            }
        }
    }
    __syncthreads();

    if (MODE == 0) {
        for (int i = tid; i < 512; i += 256) {
            int row = i >> 2, ch = i & 3;
            *(uint4*)(g_c1 + (size_t)(f0 + row) * 256 + h0 + ch * 4) = ((uint4*)stage1)[i];
        }
        for (int i = tid; i < 256; i += 256) {
            int row = i >> 1, ch = i & 1;
            *(uint4*)(g_h1h + (size_t)(f0 + row) * 256 + h0 + ch * 8) = ((uint4*)stage3)[i];
        }
    } else {
        for (int i = tid; i < 256; i += 256) {
            int row = i >> 1, ch = i & 1;
            *(uint4*)(g_h2h + (size_t)(f0 + row) * 256 + h0 + ch * 8) = ((uint4*)stage3)[i];
        }
    }
}

// ============================================================
// K5: attention over {h1,h2} + output head, ONE WARP PER FRAGMENT.
// ============================================================
__global__ __launch_bounds__(256) void attn_out(
    const float* __restrict__ Wg_frag,
    const float* __restrict__ W_out,
    const float* __restrict__ b_out)
{
    __shared__ float wst[8 * 257];   // wst[t*257 + d] = W_out[d][t]
    __shared__ float wgs[256];

    int tid = threadIdx.x;
    for (int i = tid; i < 2048; i += 256) {
        int d = i >> 3, t = i & 7;
        wst[t * 257 + d] = W_out[i];
    }
    wgs[tid] = Wg_frag[tid];
    __syncthreads();

    int w = tid >> 5, lane = tid & 31;
    int f = blockIdx.x * 8 + w;
    const __half* h1p = g_h1h + (size_t)f * 256;
    const __half* h2p = g_h2h + (size_t)f * 256;

    float h1v[8], h2v[8], wgv[8];
    float p1 = 0.f, p2 = 0.f;
#pragma unroll
    for (int j = 0; j < 8; j++) {
        int d = lane + 32 * j;
        h1v[j] = __half2float(h1p[d]);
        h2v[j] = __half2float(h2p[d]);
        wgv[j] = wgs[d];
        p1 = fmaf(h1v[j], wgv[j], p1);
        p2 = fmaf(h2v[j], wgv[j], p2);
    }
    p1 = warp_sum(p1);
    p2 = warp_sum(p2);
    float m = fmaxf(p1, p2);
    float e1 = expf(p1 - m), e2 = expf(p2 - m);
    float inv = 1.0f / (e1 + e2);

    float o[8] = {0.f, 0.f, 0.f, 0.f, 0.f, 0.f, 0.f, 0.f};
#pragma unroll
    for (int j = 0; j < 8; j++) {
        int d = lane + 32 * j;
        float fr = (e1 * h1v[j] + e2 * h2v[j]) * inv;
#pragma unroll
        for (int t = 0; t < 8; t++)
            o[t] = fmaf(fr, wst[t * 257 + d], o[t]);
    }
#pragma unroll
    for (int t = 0; t < 8; t++) o[t] = warp_sum(o[t]);

    if (lane == 0) {
        float4 b0 = *(const float4*)b_out;
        float4 b1 = *(const float4*)(b_out + 4);
        float4 v0 = make_float4(fmaxf(o[0] + b0.x, 0.f), fmaxf(o[1] + b0.y, 0.f),
                                fmaxf(o[2] + b0.z, 0.f), fmaxf(o[3] + b0.w, 0.f));
        float4 v1 = make_float4(fmaxf(o[4] + b1.x, 0.f), fmaxf(o[5] + b1.y, 0.f),
                                fmaxf(o[6] + b1.z, 0.f), fmaxf(o[7] + b1.w, 0.f));
        *(float4*)&g_fragout[(size_t)f * 8]     = v0;
        *(float4*)&g_fragout[(size_t)f * 8 + 4] = v1;
    }
}

// ============================================================
// K6: combine scatter-sum
// ============================================================
__global__ __launch_bounds__(256) void combine_kernel(
    const int* __restrict__ src, float* __restrict__ out)
{
    int idx = blockIdx.x * 256 + threadIdx.x;
    if (idx >= N_OUTN * TOUT) return;
    int n = idx >> 3, t = idx & 7;
    float s = 0.f;
#pragma unroll
    for (int d = 0; d < 4; d++)
        s += g_fragout[(size_t)src[n * 4 + d] * 8 + t];
    out[idx] = s;
}

// ============================================================
extern "C" void kernel_launch(void* const* d_in, const int* in_sizes, int n_in,
                              void* d_out, int out_size)
{
    const float* feature = (const float*)d_in[0];
    const float* WgL     = (const float*)d_in[1];
    const float* WgR     = (const float*)d_in[2];
    const float* W_ih    = (const float*)d_in[3];
    const float* W_hh    = (const float*)d_in[4];
    const float* b_ih    = (const float*)d_in[5];
    const float* b_hh    = (const float*)d_in[6];
    const float* Wg_frag = (const float*)d_in[7];
    const float* W_out   = (const float*)d_in[8];
    const float* b_out   = (const float*)d_in[9];
    const int* lost      = (const int*)d_in[10];
    const int* ret       = (const int*)d_in[11];
    const int* join      = (const int*)d_in[12];
    const int* comb      = (const int*)d_in[13];
    float* out = (float*)d_out;

    const int DSM = 49152;   // 4 x (8KB A + 4KB B)
    cudaFuncSetAttribute(gemm_fused<0>, cudaFuncAttributeMaxDynamicSharedMemorySize, DSM);
    cudaFuncSetAttribute(gemm_fused<1>, cudaFuncAttributeMaxDynamicSharedMemorySize, DSM);

    // K-1: feature fp32 -> half table
    conv_feat<<<(N_MONO * FDIM) / 1024, 256>>>(feature);

    // K0: interleaved half weights + bias
    conv_w<<<(1024 * 768 + 255) / 256, 256>>>(W_ih, W_hh, b_ih, b_hh);

    // K1: cleavage attention (warp per node, vectorized gathers)
    cleav_kernel<<<N_CLEAV / 8, 256>>>(WgL, WgR, lost, ret);

    // GEMM-A: step0 fused (K=512)
    gemm_fused<0><<<dim3(16, N_FRAG / 128), 256, DSM>>>(join);

    // GEMM-B: concat GEMM (K=768) + step1 fused
    gemm_fused<1><<<dim3(16, N_FRAG / 128), 256, DSM>>>(join);

    // K5: attention + output head (warp per fragment)
    attn_out<<<N_FRAG / 8, 256>>>(Wg_frag, W_out, b_out);

    // K6: combine scatter-sum
    combine_kernel<<<(N_OUTN * TOUT + 255) / 256, 256>>>(comb, out);
}

// round 16
// speedup vs baseline: 1.1037x; 1.1037x over previous
#include <cuda_runtime.h>
#include <cuda_fp16.h>
#include <math.h>
#include <stdint.h>

#define FDIM 256
#define TOUT 8
#define N_MONO 150000
#define N_CLEAV 100000
#define N_FRAG 80000
#define N_OUTN 40000

// ---- scratch (device globals: allocation-free rule) ----
__device__ __half g_feat_h[(size_t)N_MONO * FDIM];         // half feature table (77MB)
__device__ __half g_cleav_h[(size_t)N_CLEAV * 2 * FDIM];   // [100000, 512] half
__device__ float  g_c1[(size_t)N_FRAG * FDIM];             // [80000, 256]
__device__ __half g_h1h[(size_t)N_FRAG * FDIM];            // h1 (half)
__device__ __half g_h2h[(size_t)N_FRAG * FDIM];            // h2 (half)
__device__ float  g_fragout[(size_t)N_FRAG * TOUT];
__device__ __half g_Wcat_h[1024 * 768];                    // interleaved [Wih|Whh]
__device__ float  g_bias[1024];                            // interleaved b_ih+b_hh

__device__ __forceinline__ float warp_sum(float v) {
#pragma unroll
    for (int o = 16; o; o >>= 1) v += __shfl_xor_sync(0xffffffffu, v, o);
    return v;
}
__device__ __forceinline__ float sigf(float x) { return 1.0f / (1.0f + expf(-x)); }

__device__ __forceinline__ uint32_t smem_u32(const void* p) {
    uint32_t a;
    asm("{ .reg .u64 t; cvta.to.shared.u64 t, %1; cvt.u32.u64 %0, t; }" : "=r"(a) : "l"(p));
    return a;
}
__device__ __forceinline__ void ldmx4(uint32_t* r, uint32_t addr) {
    asm volatile("ldmatrix.sync.aligned.m8n8.x4.shared.b16 {%0,%1,%2,%3}, [%4];"
        : "=r"(r[0]), "=r"(r[1]), "=r"(r[2]), "=r"(r[3]) : "r"(addr));
}
__device__ __forceinline__ void mma_f16(float* d, const uint32_t* a, const uint32_t* b) {
    asm volatile(
        "mma.sync.aligned.m16n8k16.row.col.f32.f16.f16.f32 "
        "{%0,%1,%2,%3}, {%4,%5,%6,%7}, {%8,%9}, {%0,%1,%2,%3};"
        : "+f"(d[0]), "+f"(d[1]), "+f"(d[2]), "+f"(d[3])
        : "r"(a[0]), "r"(a[1]), "r"(a[2]), "r"(a[3]), "r"(b[0]), "r"(b[1]));
}
#define CP_ASYNC16(dst, src) \
    asm volatile("cp.async.cg.shared.global [%0], [%1], 16;" :: "r"(dst), "l"(src))
#define CP_COMMIT() asm volatile("cp.async.commit_group;" ::: "memory")
#define CP_WAIT(n)  asm volatile("cp.async.wait_group %0;" :: "n"(n) : "memory")

// ============================================================
// K0: merged prep — feature fp32->half table AND interleaved weights/bias.
// Blocks [0, 37500): feature conversion (4 elems/thread).
// Blocks [37500, 40572): weight interleave (col' = 4h+q, q:0=i,1=g,2=f,3=o).
// ============================================================
__global__ __launch_bounds__(256) void conv_all(
    const float* __restrict__ feature,
    const float* __restrict__ Wih, const float* __restrict__ Whh,
    const float* __restrict__ bih, const float* __restrict__ bhh)
{
    int b = blockIdx.x;
    if (b < 37500) {
        size_t i = ((size_t)b * 256 + threadIdx.x) * 4;
        float4 v = *(const float4*)(feature + i);
        __half2 h0 = __floats2half2_rn(v.x, v.y);
        __half2 h1 = __floats2half2_rn(v.z, v.w);
        *(uint2*)(g_feat_h + i) = make_uint2(
            *(const uint32_t*)&h0, *(const uint32_t*)&h1);
    } else {
        int idx = (b - 37500) * 256 + threadIdx.x;
        if (idx >= 1024 * 768) return;
        int rp = idx / 768, k = idx % 768;
        int h = rp >> 2, q = rp & 3;
        int orig = (q == 0) ? h : (q == 1) ? 512 + h : (q == 2) ? 256 + h : 768 + h;
        float v = (k < 512) ? Wih[orig * 512 + k] : Whh[orig * 256 + (k - 512)];
        g_Wcat_h[idx] = __float2half_rn(v);
        if (k == 0) g_bias[rp] = bih[orig] + bhh[orig];
    }
}

// ============================================================
// K1: cleavage attention, ONE WARP PER NODE (8 nodes/block).
// ============================================================
__global__ __launch_bounds__(256) void cleav_kernel(
    const float* __restrict__ WgL,
    const float* __restrict__ WgR,
    const int* __restrict__ lost_src,
    const int* __restrict__ ret_src)
{
    int w = threadIdx.x >> 5, lane = threadIdx.x & 31;
    int i = blockIdx.x * 8 + w;

    int idx = 0;
    if (lane < 4)      idx = lost_src[i * 4 + lane];
    else if (lane < 8) idx = ret_src[i * 4 + (lane - 4)];
    int rows[8];
#pragma unroll
    for (int r = 0; r < 8; r++) rows[r] = __shfl_sync(0xffffffffu, idx, r);

    int d0 = lane * 8;
    float4 la = *(const float4*)(WgL + d0);
    float4 lb = *(const float4*)(WgL + d0 + 4);
    float4 ra = *(const float4*)(WgR + d0);
    float4 rb = *(const float4*)(WgR + d0 + 4);
    float wgl[8] = {la.x, la.y, la.z, la.w, lb.x, lb.y, lb.z, lb.w};
    float wgr[8] = {ra.x, ra.y, ra.z, ra.w, rb.x, rb.y, rb.z, rb.w};

    uint4 rv[8];
    float lg[8];
#pragma unroll
    for (int r = 0; r < 8; r++) {
        rv[r] = *(const uint4*)(g_feat_h + (size_t)rows[r] * FDIM + d0);
        const __half* hp = (const __half*)&rv[r];
        float p = 0.f;
#pragma unroll
        for (int j = 0; j < 8; j++)
            p = fmaf(__half2float(hp[j]), (r < 4) ? wgl[j] : wgr[j], p);
        lg[r] = warp_sum(p);
    }

    {
        float m = fmaxf(fmaxf(lg[0], lg[1]), fmaxf(lg[2], lg[3]));
        float e0 = expf(lg[0] - m), e1 = expf(lg[1] - m);
        float e2 = expf(lg[2] - m), e3 = expf(lg[3] - m);
        float inv = 1.0f / (e0 + e1 + e2 + e3);
        e0 *= inv; e1 *= inv; e2 *= inv; e3 *= inv;
        const __half* h0 = (const __half*)&rv[0];
        const __half* h1 = (const __half*)&rv[1];
        const __half* h2 = (const __half*)&rv[2];
        const __half* h3 = (const __half*)&rv[3];
        __half ov[8];
#pragma unroll
        for (int j = 0; j < 8; j++) {
            float s = e0 * __half2float(h0[j]) + e1 * __half2float(h1[j])
                    + e2 * __half2float(h2[j]) + e3 * __half2float(h3[j]);
            ov[j] = __float2half_rn(s);
        }
        *(uint4*)(g_cleav_h + (size_t)i * 2 * FDIM + d0) = *(const uint4*)ov;
    }
    {
        float m = fmaxf(fmaxf(lg[4], lg[5]), fmaxf(lg[6], lg[7]));
        float e0 = expf(lg[4] - m), e1 = expf(lg[5] - m);
        float e2 = expf(lg[6] - m), e3 = expf(lg[7] - m);
        float inv = 1.0f / (e0 + e1 + e2 + e3);
        e0 *= inv; e1 *= inv; e2 *= inv; e3 *= inv;
        const __half* h0 = (const __half*)&rv[4];
        const __half* h1 = (const __half*)&rv[5];
        const __half* h2 = (const __half*)&rv[6];
        const __half* h3 = (const __half*)&rv[7];
        __half ov[8];
#pragma unroll
        for (int j = 0; j < 8; j++) {
            float s = e0 * __half2float(h0[j]) + e1 * __half2float(h1[j])
                    + e2 * __half2float(h2[j]) + e3 * __half2float(h3[j]);
            ov[j] = __float2half_rn(s);
        }
        *(uint4*)(g_cleav_h + (size_t)i * 2 * FDIM + FDIM + d0) = *(const uint4*)ov;
    }
}

// ============================================================
// Fused fp16 GEMM + LSTM-step epilogue — R14 configuration exactly:
// 6-slot cp.async ring, 5-stage lookahead, wait_group(4), one barrier
// per stage (WAR-safe: validated R11), sentinel empty commits in the
// tail (validated R9), FULLY unrolled mainloop (R15 showed partial
// unroll regresses).
// MODE 0: gates0 = cleav[join even] @ Wcat[:, :512]^T + bias  -> step0 -> c1,h1h
// MODE 1: gates1 = [cleav[join odd] | h1h] @ Wcat^T + bias    -> step1 -> h2h
// BM=128, BN=64, BK=32, 256 threads (8 warps, 4x2), warp tile 32x32.
// Dynamic smem: A slots 6x8KB at [0,49152), B slots 6x4KB at [49152,73728).
// ============================================================
template <int MODE>
__global__ __launch_bounds__(256, 3) void gemm_fused(const int* __restrict__ join)
{
    constexpr int K = (MODE == 0) ? 512 : 768;
    constexpr int NS = K >> 5;

    extern __shared__ __align__(16) char dsm[];
    __shared__ int sidx[128];

    int tid = threadIdx.x;
    int bm = blockIdx.y * 128;
    int bn = blockIdx.x * 64;

    if (tid < 128) sidx[tid] = join[2 * (bm + tid) + MODE];
    __syncthreads();

    // A load mapping: 128 rows x 64B, 2 chunks/thread
    int lr = tid >> 1, lh = tid & 1;
    const __half* arow_c = g_cleav_h + (size_t)sidx[lr] * 512;
    const __half* arow_h = g_h1h + (size_t)(bm + lr) * 256 - 512;  // valid for k0>=512
    int swa = (lr >> 1) & 3;
    uint32_t stA0 = lr * 64 + (((2 * lh)     ^ swa) << 4);
    uint32_t stA1 = lr * 64 + (((2 * lh + 1) ^ swa) << 4);

    // B load mapping: 64 rows x 64B, 1 chunk/thread
    int rb = tid >> 2, cb = tid & 3;
    const __half* browB = g_Wcat_h + (size_t)(bn + rb) * 768;
    uint32_t stB = rb * 64 + ((cb ^ ((rb >> 1) & 3)) << 4);

    uint32_t a_sb = smem_u32(dsm);

    int w = tid >> 5, lane = tid & 31;
    int wm = w & 3, wn = w >> 2;
    uint32_t a_addr[2], b_addr[2];
#pragma unroll
    for (int mt = 0; mt < 2; mt++) {
        int row = wm * 32 + mt * 16 + (lane & 7) + 8 * ((lane >> 3) & 1);
        int jj = (lane >> 4) & 1;
        a_addr[mt] = row * 64 + ((jj ^ ((row >> 1) & 3)) << 4);
    }
#pragma unroll
    for (int p = 0; p < 2; p++) {
        int row = wn * 32 + p * 16 + (lane & 7) + 8 * ((lane >> 4) & 1);
        int jj = (lane >> 3) & 1;
        b_addr[p] = row * 64 + ((jj ^ ((row >> 1) & 3)) << 4);
    }

    float acc[2][4][4];
#pragma unroll
    for (int mt = 0; mt < 2; mt++)
#pragma unroll
        for (int nt = 0; nt < 4; nt++)
#pragma unroll
            for (int q = 0; q < 4; q++) acc[mt][nt][q] = 0.f;

#define ISSUE_STAGE(S, SLOT) do {                                             \
        int _k0 = (S) << 5;                                                   \
        const __half* _as = (MODE == 0 || _k0 < 512) ? (arow_c + _k0)         \
                                                     : (arow_h + _k0);        \
        uint32_t _ab = a_sb + (uint32_t)(SLOT) * 8192;                        \
        uint32_t _bb = a_sb + 49152 + (uint32_t)(SLOT) * 4096;                \
        CP_ASYNC16(_ab + stA0, _as + 16 * lh);                                \
        CP_ASYNC16(_ab + stA1, _as + 16 * lh + 8);                            \
        CP_ASYNC16(_bb + stB, browB + _k0 + cb * 8);                          \
        CP_COMMIT();                                                          \
    } while (0)

    ISSUE_STAGE(0, 0);
    ISSUE_STAGE(1, 1);
    ISSUE_STAGE(2, 2);
    ISSUE_STAGE(3, 3);
    ISSUE_STAGE(4, 4);

#pragma unroll
    for (int s = 0; s < NS; s++) {
        CP_WAIT(4);           // group s certified (in-order + sentinels)
        __syncthreads();      // all warps finished compute s-1; stage s visible
        if (s + 5 < NS) {
            ISSUE_STAGE(s + 5, (s + 5) % 6);
        } else {
            CP_COMMIT();      // sentinel: keeps wait_group(4) accounting exact
        }

        uint32_t abase = a_sb + (uint32_t)(s % 6) * 8192;
        uint32_t bbase = a_sb + 49152 + (uint32_t)(s % 6) * 4096;
#pragma unroll
        for (int kk = 0; kk < 2; kk++) {
            uint32_t koff = kk << 5;
            uint32_t af[2][4];
            ldmx4(af[0], abase + (a_addr[0] ^ koff));
            ldmx4(af[1], abase + (a_addr[1] ^ koff));
            uint32_t bf[2][4];
            ldmx4(bf[0], bbase + (b_addr[0] ^ koff));
            ldmx4(bf[1], bbase + (b_addr[1] ^ koff));
#pragma unroll
            for (int mt = 0; mt < 2; mt++)
#pragma unroll
                for (int p = 0; p < 2; p++) {
                    mma_f16(acc[mt][2 * p],     af[mt], &bf[p][0]);
                    mma_f16(acc[mt][2 * p + 1], af[mt], &bf[p][2]);
                }
        }
    }
    CP_WAIT(0);
    __syncthreads();
#undef ISSUE_STAGE

    // ================= fused LSTM epilogue =================
    float*  stage1 = (float*)dsm;                 // c1 tile [128][16] fp32
    __half* stage3 = (__half*)(dsm + 8192);       // h1h or h2h tile [128][16]

    int f0 = bm, h0 = bn >> 2;

    if (MODE == 1) {
        for (int i = tid; i < 512; i += 256) {
            int row = i >> 2, ch = i & 3;
            ((uint4*)stage1)[i] =
                *(const uint4*)(g_c1 + (size_t)(f0 + row) * 256 + h0 + ch * 4);
        }
        __syncthreads();
    }

    int g = lane >> 2, c = lane & 3;
#pragma unroll
    for (int mt = 0; mt < 2; mt++) {
#pragma unroll
        for (int nt = 0; nt < 4; nt++) {
            int col = bn + wn * 32 + nt * 8 + 2 * c;
            float bv0 = __ldg(g_bias + col);
            float bv1 = __ldg(g_bias + col + 1);
            float x0 = acc[mt][nt][0] + bv0;   // even c: i(r0); odd c: f(r0)
            float x1 = acc[mt][nt][1] + bv1;   // even c: g(r0); odd c: o(r0)
            float x2 = acc[mt][nt][2] + bv0;   // row r1
            float x3 = acc[mt][nt][3] + bv1;
            float a0 = sigf(x0) * tanhf(x1);   // meaningful on even-c lanes
            float a1 = sigf(x2) * tanhf(x3);
            float b0 = __shfl_xor_sync(0xffffffffu, a0, 1);
            float b1 = __shfl_xor_sync(0xffffffffu, a1, 1);
            if (c & 1) {
                int hl = wn * 8 + nt * 2 + (c >> 1);
                int rl = wm * 32 + mt * 16 + g;
                if (MODE == 0) {
                    float h1a = sigf(x1) * tanhf(b0);
                    float h1b = sigf(x3) * tanhf(b1);
                    stage1[rl * 16 + hl] = b0;
                    stage1[(rl + 8) * 16 + hl] = b1;
                    stage3[rl * 16 + hl] = __float2half_rn(h1a);
                    stage3[(rl + 8) * 16 + hl] = __float2half_rn(h1b);
                } else {
                    float c1a = stage1[rl * 16 + hl];
                    float c1b = stage1[(rl + 8) * 16 + hl];
                    float c2a = sigf(x0) * c1a + b0;
                    float c2b = sigf(x2) * c1b + b1;
                    stage3[rl * 16 + hl] = __float2half_rn(sigf(x1) * tanhf(c2a));
                    stage3[(rl + 8) * 16 + hl] = __float2half_rn(sigf(x3) * tanhf(c2b));
                }
            }
        }
    }
    __syncthreads();

    if (MODE == 0) {
        for (int i = tid; i < 512; i += 256) {
            int row = i >> 2, ch = i & 3;
            *(uint4*)(g_c1 + (size_t)(f0 + row) * 256 + h0 + ch * 4) = ((uint4*)stage1)[i];
        }
        for (int i = tid; i < 256; i += 256) {
            int row = i >> 1, ch = i & 1;
            *(uint4*)(g_h1h + (size_t)(f0 + row) * 256 + h0 + ch * 8) = ((uint4*)stage3)[i];
        }
    } else {
        for (int i = tid; i < 256; i += 256) {
            int row = i >> 1, ch = i & 1;
            *(uint4*)(g_h2h + (size_t)(f0 + row) * 256 + h0 + ch * 8) = ((uint4*)stage3)[i];
        }
    }
}

// ============================================================
// K5: attention over {h1,h2} + output head, ONE WARP PER FRAGMENT.
// ============================================================
__global__ __launch_bounds__(256) void attn_out(
    const float* __restrict__ Wg_frag,
    const float* __restrict__ W_out,
    const float* __restrict__ b_out)
{
    __shared__ float wst[8 * 257];   // wst[t*257 + d] = W_out[d][t]
    __shared__ float wgs[256];

    int tid = threadIdx.x;
    for (int i = tid; i < 2048; i += 256) {
        int d = i >> 3, t = i & 7;
        wst[t * 257 + d] = W_out[i];
    }
    wgs[tid] = Wg_frag[tid];
    __syncthreads();

    int w = tid >> 5, lane = tid & 31;
    int f = blockIdx.x * 8 + w;
    const __half* h1p = g_h1h + (size_t)f * 256;
    const __half* h2p = g_h2h + (size_t)f * 256;

    float h1v[8], h2v[8], wgv[8];
    float p1 = 0.f, p2 = 0.f;
#pragma unroll
    for (int j = 0; j < 8; j++) {
        int d = lane + 32 * j;
        h1v[j] = __half2float(h1p[d]);
        h2v[j] = __half2float(h2p[d]);
        wgv[j] = wgs[d];
        p1 = fmaf(h1v[j], wgv[j], p1);
        p2 = fmaf(h2v[j], wgv[j], p2);
    }
    p1 = warp_sum(p1);
    p2 = warp_sum(p2);
    float m = fmaxf(p1, p2);
    float e1 = expf(p1 - m), e2 = expf(p2 - m);
    float inv = 1.0f / (e1 + e2);

    float o[8] = {0.f, 0.f, 0.f, 0.f, 0.f, 0.f, 0.f, 0.f};
#pragma unroll
    for (int j = 0; j < 8; j++) {
        int d = lane + 32 * j;
        float fr = (e1 * h1v[j] + e2 * h2v[j]) * inv;
#pragma unroll
        for (int t = 0; t < 8; t++)
            o[t] = fmaf(fr, wst[t * 257 + d], o[t]);
    }
#pragma unroll
    for (int t = 0; t < 8; t++) o[t] = warp_sum(o[t]);

    if (lane == 0) {
        float4 b0 = *(const float4*)b_out;
        float4 b1 = *(const float4*)(b_out + 4);
        float4 v0 = make_float4(fmaxf(o[0] + b0.x, 0.f), fmaxf(o[1] + b0.y, 0.f),
                                fmaxf(o[2] + b0.z, 0.f), fmaxf(o[3] + b0.w, 0.f));
        float4 v1 = make_float4(fmaxf(o[4] + b1.x, 0.f), fmaxf(o[5] + b1.y, 0.f),
                                fmaxf(o[6] + b1.z, 0.f), fmaxf(o[7] + b1.w, 0.f));
        *(float4*)&g_fragout[(size_t)f * 8]     = v0;
        *(float4*)&g_fragout[(size_t)f * 8 + 4] = v1;
    }
}

// ============================================================
// K6: combine scatter-sum, ONE THREAD PER OUTPUT ROW.
// Each fragout row is 32B: read as two float4s (coalesced per row).
// ============================================================
__global__ __launch_bounds__(256) void combine_kernel(
    const int* __restrict__ src, float* __restrict__ out)
{
    int n = blockIdx.x * 256 + threadIdx.x;
    if (n >= N_OUTN) return;
    int4 s4 = *(const int4*)(src + n * 4);
    int idxs[4] = {s4.x, s4.y, s4.z, s4.w};
    float4 acc0 = make_float4(0.f, 0.f, 0.f, 0.f);
    float4 acc1 = make_float4(0.f, 0.f, 0.f, 0.f);
#pragma unroll
    for (int d = 0; d < 4; d++) {
        const float* fp = g_fragout + (size_t)idxs[d] * 8;
        float4 a = *(const float4*)fp;
        float4 b = *(const float4*)(fp + 4);
        acc0.x += a.x; acc0.y += a.y; acc0.z += a.z; acc0.w += a.w;
        acc1.x += b.x; acc1.y += b.y; acc1.z += b.z; acc1.w += b.w;
    }
    *(float4*)(out + (size_t)n * 8)     = acc0;
    *(float4*)(out + (size_t)n * 8 + 4) = acc1;
}

// ============================================================
extern "C" void kernel_launch(void* const* d_in, const int* in_sizes, int n_in,
                              void* d_out, int out_size)
{
    const float* feature = (const float*)d_in[0];
    const float* WgL     = (const float*)d_in[1];
    const float* WgR     = (const float*)d_in[2];
    const float* W_ih    = (const float*)d_in[3];
    const float* W_hh    = (const float*)d_in[4];
    const float* b_ih    = (const float*)d_in[5];
    const float* b_hh    = (const float*)d_in[6];
    const float* Wg_frag = (const float*)d_in[7];
    const float* W_out   = (const float*)d_in[8];
    const float* b_out   = (const float*)d_in[9];
    const int* lost      = (const int*)d_in[10];
    const int* ret       = (const int*)d_in[11];
    const int* join      = (const int*)d_in[12];
    const int* comb      = (const int*)d_in[13];
    float* out = (float*)d_out;

    const int DSM = 73728;   // 6 x (8KB A + 4KB B)
    cudaFuncSetAttribute(gemm_fused<0>, cudaFuncAttributeMaxDynamicSharedMemorySize, DSM);
    cudaFuncSetAttribute(gemm_fused<1>, cudaFuncAttributeMaxDynamicSharedMemorySize, DSM);

    // K0: merged prep (feature table + interleaved weights/bias)
    conv_all<<<37500 + 3072, 256>>>(feature, W_ih, W_hh, b_ih, b_hh);

    // K1: cleavage attention (warp per node, vectorized gathers)
    cleav_kernel<<<N_CLEAV / 8, 256>>>(WgL, WgR, lost, ret);

    // GEMM-A: step0 fused (K=512)
    gemm_fused<0><<<dim3(16, N_FRAG / 128), 256, DSM>>>(join);

    // GEMM-B: concat GEMM (K=768) + step1 fused
    gemm_fused<1><<<dim3(16, N_FRAG / 128), 256, DSM>>>(join);

    // K5: attention + output head (warp per fragment)
    attn_out<<<N_FRAG / 8, 256>>>(Wg_frag, W_out, b_out);

    // K6: combine scatter-sum (thread per output row, float4 reads)
    combine_kernel<<<(N_OUTN + 255) / 256, 256>>>(comb, out);
}

// round 17
// speedup vs baseline: 1.1838x; 1.0726x over previous
#include <cuda_runtime.h>
#include <cuda_fp16.h>
#include <math.h>
#include <stdint.h>

#define FDIM 256
#define TOUT 8
#define N_MONO 150000
#define N_CLEAV 100000
#define N_FRAG 80000
#define N_OUTN 40000

// ---- scratch (device globals: allocation-free rule) ----
__device__ __half g_feat_h[(size_t)N_MONO * FDIM];         // half feature table (77MB)
__device__ __half g_cleav_h[(size_t)N_CLEAV * 2 * FDIM];   // [100000, 512] half
__device__ float  g_c1[(size_t)N_FRAG * FDIM];             // [80000, 256]
__device__ __half g_h1h[(size_t)N_FRAG * FDIM];            // h1 (half)
__device__ __half g_h2h[(size_t)N_FRAG * FDIM];            // h2 (half)
__device__ float  g_fragout[(size_t)N_FRAG * TOUT];
__device__ __half g_Wcat_h[1024 * 768];                    // quad-interleaved [Wih|Whh] (GEMM-B)
__device__ float  g_bias[1024];                            // quad-interleaved bias
__device__ __half g_WcatA_h[768 * 512];                    // step0 weights: (i,g) pairs + o block
__device__ float  g_biasA[768];

__device__ __forceinline__ float warp_sum(float v) {
#pragma unroll
    for (int o = 16; o; o >>= 1) v += __shfl_xor_sync(0xffffffffu, v, o);
    return v;
}
__device__ __forceinline__ float sigf(float x) { return 1.0f / (1.0f + expf(-x)); }

__device__ __forceinline__ uint32_t smem_u32(const void* p) {
    uint32_t a;
    asm("{ .reg .u64 t; cvta.to.shared.u64 t, %1; cvt.u32.u64 %0, t; }" : "=r"(a) : "l"(p));
    return a;
}
__device__ __forceinline__ void ldmx4(uint32_t* r, uint32_t addr) {
    asm volatile("ldmatrix.sync.aligned.m8n8.x4.shared.b16 {%0,%1,%2,%3}, [%4];"
        : "=r"(r[0]), "=r"(r[1]), "=r"(r[2]), "=r"(r[3]) : "r"(addr));
}
__device__ __forceinline__ void mma_f16(float* d, const uint32_t* a, const uint32_t* b) {
    asm volatile(
        "mma.sync.aligned.m16n8k16.row.col.f32.f16.f16.f32 "
        "{%0,%1,%2,%3}, {%4,%5,%6,%7}, {%8,%9}, {%0,%1,%2,%3};"
        : "+f"(d[0]), "+f"(d[1]), "+f"(d[2]), "+f"(d[3])
        : "r"(a[0]), "r"(a[1]), "r"(a[2]), "r"(a[3]), "r"(b[0]), "r"(b[1]));
}
#define CP_ASYNC16(dst, src) \
    asm volatile("cp.async.cg.shared.global [%0], [%1], 16;" :: "r"(dst), "l"(src))
#define CP_COMMIT() asm volatile("cp.async.commit_group;" ::: "memory")
#define CP_WAIT(n)  asm volatile("cp.async.wait_group %0;" :: "n"(n) : "memory")

// ============================================================
// K0: merged prep.
// Blocks [0,37500): feature fp32->half.
// Blocks [37500,40572): quad weights (col'=4h+q, q:0=i,1=g,2=f,3=o).
// Blocks [40572,42108): step0 weights: rows [0,512)=(i,g) pairs
//   (row 2h=i_h, 2h+1=g_h), rows [512,768)=o_h. K=512 (Wih only).
// ============================================================
__global__ __launch_bounds__(256) void conv_all(
    const float* __restrict__ feature,
    const float* __restrict__ Wih, const float* __restrict__ Whh,
    const float* __restrict__ bih, const float* __restrict__ bhh)
{
    int b = blockIdx.x;
    if (b < 37500) {
        size_t i = ((size_t)b * 256 + threadIdx.x) * 4;
        float4 v = *(const float4*)(feature + i);
        __half2 h0 = __floats2half2_rn(v.x, v.y);
        __half2 h1 = __floats2half2_rn(v.z, v.w);
        *(uint2*)(g_feat_h + i) = make_uint2(
            *(const uint32_t*)&h0, *(const uint32_t*)&h1);
    } else if (b < 40572) {
        int idx = (b - 37500) * 256 + threadIdx.x;
        int rp = idx / 768, k = idx % 768;
        int h = rp >> 2, q = rp & 3;
        int orig = (q == 0) ? h : (q == 1) ? 512 + h : (q == 2) ? 256 + h : 768 + h;
        float v = (k < 512) ? Wih[orig * 512 + k] : Whh[orig * 256 + (k - 512)];
        g_Wcat_h[idx] = __float2half_rn(v);
        if (k == 0) g_bias[rp] = bih[orig] + bhh[orig];
    } else {
        int idx = (b - 40572) * 256 + threadIdx.x;
        int rp = idx >> 9, k = idx & 511;
        int orig;
        if (rp < 512) { int h = rp >> 1; orig = (rp & 1) ? 512 + h : h; }
        else          { orig = 768 + (rp - 512); }
        g_WcatA_h[idx] = __float2half_rn(Wih[orig * 512 + k]);
        if (k == 0) g_biasA[rp] = bih[orig] + bhh[orig];
    }
}

// ============================================================
// K1: cleavage attention, ONE WARP PER NODE (8 nodes/block).
// ============================================================
__global__ __launch_bounds__(256) void cleav_kernel(
    const float* __restrict__ WgL,
    const float* __restrict__ WgR,
    const int* __restrict__ lost_src,
    const int* __restrict__ ret_src)
{
    int w = threadIdx.x >> 5, lane = threadIdx.x & 31;
    int i = blockIdx.x * 8 + w;

    int idx = 0;
    if (lane < 4)      idx = lost_src[i * 4 + lane];
    else if (lane < 8) idx = ret_src[i * 4 + (lane - 4)];
    int rows[8];
#pragma unroll
    for (int r = 0; r < 8; r++) rows[r] = __shfl_sync(0xffffffffu, idx, r);

    int d0 = lane * 8;
    float4 la = *(const float4*)(WgL + d0);
    float4 lb = *(const float4*)(WgL + d0 + 4);
    float4 ra = *(const float4*)(WgR + d0);
    float4 rb = *(const float4*)(WgR + d0 + 4);
    float wgl[8] = {la.x, la.y, la.z, la.w, lb.x, lb.y, lb.z, lb.w};
    float wgr[8] = {ra.x, ra.y, ra.z, ra.w, rb.x, rb.y, rb.z, rb.w};

    uint4 rv[8];
    float lg[8];
#pragma unroll
    for (int r = 0; r < 8; r++) {
        rv[r] = *(const uint4*)(g_feat_h + (size_t)rows[r] * FDIM + d0);
        const __half* hp = (const __half*)&rv[r];
        float p = 0.f;
#pragma unroll
        for (int j = 0; j < 8; j++)
            p = fmaf(__half2float(hp[j]), (r < 4) ? wgl[j] : wgr[j], p);
        lg[r] = warp_sum(p);
    }

    {
        float m = fmaxf(fmaxf(lg[0], lg[1]), fmaxf(lg[2], lg[3]));
        float e0 = expf(lg[0] - m), e1 = expf(lg[1] - m);
        float e2 = expf(lg[2] - m), e3 = expf(lg[3] - m);
        float inv = 1.0f / (e0 + e1 + e2 + e3);
        e0 *= inv; e1 *= inv; e2 *= inv; e3 *= inv;
        const __half* h0 = (const __half*)&rv[0];
        const __half* h1 = (const __half*)&rv[1];
        const __half* h2 = (const __half*)&rv[2];
        const __half* h3 = (const __half*)&rv[3];
        __half ov[8];
#pragma unroll
        for (int j = 0; j < 8; j++) {
            float s = e0 * __half2float(h0[j]) + e1 * __half2float(h1[j])
                    + e2 * __half2float(h2[j]) + e3 * __half2float(h3[j]);
            ov[j] = __float2half_rn(s);
        }
        *(uint4*)(g_cleav_h + (size_t)i * 2 * FDIM + d0) = *(const uint4*)ov;
    }
    {
        float m = fmaxf(fmaxf(lg[4], lg[5]), fmaxf(lg[6], lg[7]));
        float e0 = expf(lg[4] - m), e1 = expf(lg[5] - m);
        float e2 = expf(lg[6] - m), e3 = expf(lg[7] - m);
        float inv = 1.0f / (e0 + e1 + e2 + e3);
        e0 *= inv; e1 *= inv; e2 *= inv; e3 *= inv;
        const __half* h0 = (const __half*)&rv[4];
        const __half* h1 = (const __half*)&rv[5];
        const __half* h2 = (const __half*)&rv[6];
        const __half* h3 = (const __half*)&rv[7];
        __half ov[8];
#pragma unroll
        for (int j = 0; j < 8; j++) {
            float s = e0 * __half2float(h0[j]) + e1 * __half2float(h1[j])
                    + e2 * __half2float(h2[j]) + e3 * __half2float(h3[j]);
            ov[j] = __float2half_rn(s);
        }
        *(uint4*)(g_cleav_h + (size_t)i * 2 * FDIM + FDIM + d0) = *(const uint4*)ov;
    }
}

// ============================================================
// Fused fp16 GEMM + LSTM epilogues. Mainloop = R14-validated pipeline
// (6-slot ring, 5-stage lookahead, wait_group(4), one barrier/stage,
// sentinel tail commits, fully unrolled).
// MODE 0 (A1): N=512 (i,g) pairs, K=512, A=cleav[join even] -> c1
// MODE 1 (A2): N=256 o-gates,    K=512, A=cleav[join even] -> h1h (reads c1)
// MODE 2 (B):  N=1024 quads,     K=768, A=[cleav[join odd]|h1h] -> h2h (reads c1)
// BM=128, BN=64, BK=32, 256 threads (8 warps, 4x2), warp tile 32x32.
// Dynamic smem: A slots 6x8KB [0,49152), B slots 6x4KB [49152,73728).
// ============================================================
template <int MODE>
__global__ __launch_bounds__(256, 3) void gemm_fused(const int* __restrict__ join)
{
    constexpr int K = (MODE == 2) ? 768 : 512;
    constexpr int NS = K >> 5;

    extern __shared__ __align__(16) char dsm[];
    __shared__ int sidx[128];

    int tid = threadIdx.x;
    int bm = blockIdx.y * 128;
    int bn = blockIdx.x * 64;

    if (tid < 128) sidx[tid] = join[2 * (bm + tid) + ((MODE == 2) ? 1 : 0)];
    __syncthreads();

    // A load mapping: 128 rows x 64B, 2 chunks/thread
    int lr = tid >> 1, lh = tid & 1;
    const __half* arow_c = g_cleav_h + (size_t)sidx[lr] * 512;
    const __half* arow_h = g_h1h + (size_t)(bm + lr) * 256 - 512;  // MODE 2, k0>=512
    int swa = (lr >> 1) & 3;
    uint32_t stA0 = lr * 64 + (((2 * lh)     ^ swa) << 4);
    uint32_t stA1 = lr * 64 + (((2 * lh + 1) ^ swa) << 4);

    // B load mapping: 64 rows x 64B, 1 chunk/thread
    int rb = tid >> 2, cb = tid & 3;
    const __half* browB;
    if (MODE == 2)      browB = g_Wcat_h  + (size_t)(bn + rb) * 768;
    else if (MODE == 1) browB = g_WcatA_h + (size_t)(512 + bn + rb) * 512;
    else                browB = g_WcatA_h + (size_t)(bn + rb) * 512;
    uint32_t stB = rb * 64 + ((cb ^ ((rb >> 1) & 3)) << 4);

    uint32_t a_sb = smem_u32(dsm);

    int w = tid >> 5, lane = tid & 31;
    int wm = w & 3, wn = w >> 2;
    uint32_t a_addr[2], b_addr[2];
#pragma unroll
    for (int mt = 0; mt < 2; mt++) {
        int row = wm * 32 + mt * 16 + (lane & 7) + 8 * ((lane >> 3) & 1);
        int jj = (lane >> 4) & 1;
        a_addr[mt] = row * 64 + ((jj ^ ((row >> 1) & 3)) << 4);
    }
#pragma unroll
    for (int p = 0; p < 2; p++) {
        int row = wn * 32 + p * 16 + (lane & 7) + 8 * ((lane >> 4) & 1);
        int jj = (lane >> 3) & 1;
        b_addr[p] = row * 64 + ((jj ^ ((row >> 1) & 3)) << 4);
    }

    float acc[2][4][4];
#pragma unroll
    for (int mt = 0; mt < 2; mt++)
#pragma unroll
        for (int nt = 0; nt < 4; nt++)
#pragma unroll
            for (int q = 0; q < 4; q++) acc[mt][nt][q] = 0.f;

#define ISSUE_STAGE(S, SLOT) do {                                             \
        int _k0 = (S) << 5;                                                   \
        const __half* _as = (MODE != 2 || _k0 < 512) ? (arow_c + _k0)         \
                                                     : (arow_h + _k0);        \
        uint32_t _ab = a_sb + (uint32_t)(SLOT) * 8192;                        \
        uint32_t _bb = a_sb + 49152 + (uint32_t)(SLOT) * 4096;                \
        CP_ASYNC16(_ab + stA0, _as + 16 * lh);                                \
        CP_ASYNC16(_ab + stA1, _as + 16 * lh + 8);                            \
        CP_ASYNC16(_bb + stB, browB + _k0 + cb * 8);                          \
        CP_COMMIT();                                                          \
    } while (0)

    ISSUE_STAGE(0, 0);
    ISSUE_STAGE(1, 1);
    ISSUE_STAGE(2, 2);
    ISSUE_STAGE(3, 3);
    ISSUE_STAGE(4, 4);

#pragma unroll
    for (int s = 0; s < NS; s++) {
        CP_WAIT(4);           // group s certified (in-order + sentinels)
        __syncthreads();      // all warps finished compute s-1; stage s visible
        if (s + 5 < NS) {
            ISSUE_STAGE(s + 5, (s + 5) % 6);
        } else {
            CP_COMMIT();      // sentinel: keeps wait_group(4) accounting exact
        }

        uint32_t abase = a_sb + (uint32_t)(s % 6) * 8192;
        uint32_t bbase = a_sb + 49152 + (uint32_t)(s % 6) * 4096;
#pragma unroll
        for (int kk = 0; kk < 2; kk++) {
            uint32_t koff = kk << 5;
            uint32_t af[2][4];
            ldmx4(af[0], abase + (a_addr[0] ^ koff));
            ldmx4(af[1], abase + (a_addr[1] ^ koff));
            uint32_t bf[2][4];
            ldmx4(bf[0], bbase + (b_addr[0] ^ koff));
            ldmx4(bf[1], bbase + (b_addr[1] ^ koff));
#pragma unroll
            for (int mt = 0; mt < 2; mt++)
#pragma unroll
                for (int p = 0; p < 2; p++) {
                    mma_f16(acc[mt][2 * p],     af[mt], &bf[p][0]);
                    mma_f16(acc[mt][2 * p + 1], af[mt], &bf[p][2]);
                }
        }
    }
    CP_WAIT(0);
    __syncthreads();
#undef ISSUE_STAGE

    // ================= epilogues =================
    int f0 = bm;
    int g = lane >> 2, c = lane & 3;

    if (MODE == 0) {
        // c1 = sig(i)*tanh(g); thread's two adjacent cols ARE the (i,g) pair.
        float* stage = (float*)dsm;          // [128][36] fp32 (padded)
        int h0 = bn >> 1;                    // unit offset (64 cols = 32 units)
#pragma unroll
        for (int mt = 0; mt < 2; mt++) {
#pragma unroll
            for (int nt = 0; nt < 4; nt++) {
                int lcol = wn * 32 + nt * 8 + 2 * c;
                float bv0 = __ldg(g_biasA + bn + lcol);
                float bv1 = __ldg(g_biasA + bn + lcol + 1);
                float x0 = acc[mt][nt][0] + bv0;   // i, row rl
                float x1 = acc[mt][nt][1] + bv1;   // g, row rl
                float x2 = acc[mt][nt][2] + bv0;   // i, row rl+8
                float x3 = acc[mt][nt][3] + bv1;
                int ul = lcol >> 1;
                int rl = wm * 32 + mt * 16 + g;
                stage[rl * 36 + ul]       = sigf(x0) * tanhf(x1);
                stage[(rl + 8) * 36 + ul] = sigf(x2) * tanhf(x3);
            }
        }
        __syncthreads();
        for (int i = tid; i < 1024; i += 256) {
            int row = i >> 3, ch = i & 7;
            *(uint4*)(g_c1 + (size_t)(f0 + row) * 256 + h0 + ch * 4) =
                ((uint4*)(stage + row * 36))[ch];
        }
    } else if (MODE == 1) {
        // h1 = sig(o)*tanh(c1); units map 1:1 to cols.
        float*  stage1 = (float*)dsm;                 // c1 [128][68] fp32 (padded)
        __half* stage3 = (__half*)(dsm + 34816);      // h1h [128][72] half (padded)
        int u0 = bn;
        for (int i = tid; i < 2048; i += 256) {
            int row = i >> 4, ch = i & 15;
            ((uint4*)(stage1 + row * 68))[ch] =
                *(const uint4*)(g_c1 + (size_t)(f0 + row) * 256 + u0 + ch * 4);
        }
        __syncthreads();
#pragma unroll
        for (int mt = 0; mt < 2; mt++) {
#pragma unroll
            for (int nt = 0; nt < 4; nt++) {
                int lcol = wn * 32 + nt * 8 + 2 * c;
                float bv0 = __ldg(g_biasA + 512 + bn + lcol);
                float bv1 = __ldg(g_biasA + 512 + bn + lcol + 1);
                float x0 = acc[mt][nt][0] + bv0;
                float x1 = acc[mt][nt][1] + bv1;
                float x2 = acc[mt][nt][2] + bv0;
                float x3 = acc[mt][nt][3] + bv1;
                int rl = wm * 32 + mt * 16 + g;
                stage3[rl * 72 + lcol]           = __float2half_rn(sigf(x0) * tanhf(stage1[rl * 68 + lcol]));
                stage3[rl * 72 + lcol + 1]       = __float2half_rn(sigf(x1) * tanhf(stage1[rl * 68 + lcol + 1]));
                stage3[(rl + 8) * 72 + lcol]     = __float2half_rn(sigf(x2) * tanhf(stage1[(rl + 8) * 68 + lcol]));
                stage3[(rl + 8) * 72 + lcol + 1] = __float2half_rn(sigf(x3) * tanhf(stage1[(rl + 8) * 68 + lcol + 1]));
            }
        }
        __syncthreads();
        for (int i = tid; i < 1024; i += 256) {
            int row = i >> 3, ch = i & 7;
            *(uint4*)(g_h1h + (size_t)(f0 + row) * 256 + u0 + ch * 8) =
                ((uint4*)(stage3 + row * 72))[ch];
        }
    } else {
        // step1 (quad layout, shfl pairing) -> h2h   [validated R12-R16]
        float*  stage1 = (float*)dsm;                 // c1 tile [128][16] fp32
        __half* stage3 = (__half*)(dsm + 8192);       // h2h tile [128][16]
        int h0 = bn >> 2;
        for (int i = tid; i < 512; i += 256) {
            int row = i >> 2, ch = i & 3;
            ((uint4*)stage1)[i] =
                *(const uint4*)(g_c1 + (size_t)(f0 + row) * 256 + h0 + ch * 4);
        }
        __syncthreads();
#pragma unroll
        for (int mt = 0; mt < 2; mt++) {
#pragma unroll
            for (int nt = 0; nt < 4; nt++) {
                int col = bn + wn * 32 + nt * 8 + 2 * c;
                float bv0 = __ldg(g_bias + col);
                float bv1 = __ldg(g_bias + col + 1);
                float x0 = acc[mt][nt][0] + bv0;   // even c: i; odd c: f
                float x1 = acc[mt][nt][1] + bv1;   // even c: g; odd c: o
                float x2 = acc[mt][nt][2] + bv0;
                float x3 = acc[mt][nt][3] + bv1;
                float a0 = sigf(x0) * tanhf(x1);
                float a1 = sigf(x2) * tanhf(x3);
                float b0 = __shfl_xor_sync(0xffffffffu, a0, 1);
                float b1 = __shfl_xor_sync(0xffffffffu, a1, 1);
                if (c & 1) {
                    int hl = wn * 8 + nt * 2 + (c >> 1);
                    int rl = wm * 32 + mt * 16 + g;
                    float c1a = stage1[rl * 16 + hl];
                    float c1b = stage1[(rl + 8) * 16 + hl];
                    float c2a = sigf(x0) * c1a + b0;
                    float c2b = sigf(x2) * c1b + b1;
                    stage3[rl * 16 + hl] = __float2half_rn(sigf(x1) * tanhf(c2a));
                    stage3[(rl + 8) * 16 + hl] = __float2half_rn(sigf(x3) * tanhf(c2b));
                }
            }
        }
        __syncthreads();
        for (int i = tid; i < 256; i += 256) {
            int row = i >> 1, ch = i & 1;
            *(uint4*)(g_h2h + (size_t)(f0 + row) * 256 + h0 + ch * 8) = ((uint4*)stage3)[i];
        }
    }
}

// ============================================================
// K5: attention over {h1,h2} + output head, ONE WARP PER FRAGMENT.
// ============================================================
__global__ __launch_bounds__(256) void attn_out(
    const float* __restrict__ Wg_frag,
    const float* __restrict__ W_out,
    const float* __restrict__ b_out)
{
    __shared__ float wst[8 * 257];
    __shared__ float wgs[256];

    int tid = threadIdx.x;
    for (int i = tid; i < 2048; i += 256) {
        int d = i >> 3, t = i & 7;
        wst[t * 257 + d] = W_out[i];
    }
    wgs[tid] = Wg_frag[tid];
    __syncthreads();

    int w = tid >> 5, lane = tid & 31;
    int f = blockIdx.x * 8 + w;
    const __half* h1p = g_h1h + (size_t)f * 256;
    const __half* h2p = g_h2h + (size_t)f * 256;

    float h1v[8], h2v[8], wgv[8];
    float p1 = 0.f, p2 = 0.f;
#pragma unroll
    for (int j = 0; j < 8; j++) {
        int d = lane + 32 * j;
        h1v[j] = __half2float(h1p[d]);
        h2v[j] = __half2float(h2p[d]);
        wgv[j] = wgs[d];
        p1 = fmaf(h1v[j], wgv[j], p1);
        p2 = fmaf(h2v[j], wgv[j], p2);
    }
    p1 = warp_sum(p1);
    p2 = warp_sum(p2);
    float m = fmaxf(p1, p2);
    float e1 = expf(p1 - m), e2 = expf(p2 - m);
    float inv = 1.0f / (e1 + e2);

    float o[8] = {0.f, 0.f, 0.f, 0.f, 0.f, 0.f, 0.f, 0.f};
#pragma unroll
    for (int j = 0; j < 8; j++) {
        int d = lane + 32 * j;
        float fr = (e1 * h1v[j] + e2 * h2v[j]) * inv;
#pragma unroll
        for (int t = 0; t < 8; t++)
            o[t] = fmaf(fr, wst[t * 257 + d], o[t]);
    }
#pragma unroll
    for (int t = 0; t < 8; t++) o[t] = warp_sum(o[t]);

    if (lane == 0) {
        float4 b0 = *(const float4*)b_out;
        float4 b1 = *(const float4*)(b_out + 4);
        float4 v0 = make_float4(fmaxf(o[0] + b0.x, 0.f), fmaxf(o[1] + b0.y, 0.f),
                                fmaxf(o[2] + b0.z, 0.f), fmaxf(o[3] + b0.w, 0.f));
        float4 v1 = make_float4(fmaxf(o[4] + b1.x, 0.f), fmaxf(o[5] + b1.y, 0.f),
                                fmaxf(o[6] + b1.z, 0.f), fmaxf(o[7] + b1.w, 0.f));
        *(float4*)&g_fragout[(size_t)f * 8]     = v0;
        *(float4*)&g_fragout[(size_t)f * 8 + 4] = v1;
    }
}

// ============================================================
// K6: combine scatter-sum, ONE THREAD PER OUTPUT ROW.
// ============================================================
__global__ __launch_bounds__(256) void combine_kernel(
    const int* __restrict__ src, float* __restrict__ out)
{
    int n = blockIdx.x * 256 + threadIdx.x;
    if (n >= N_OUTN) return;
    int4 s4 = *(const int4*)(src + n * 4);
    int idxs[4] = {s4.x, s4.y, s4.z, s4.w};
    float4 acc0 = make_float4(0.f, 0.f, 0.f, 0.f);
    float4 acc1 = make_float4(0.f, 0.f, 0.f, 0.f);
#pragma unroll
    for (int d = 0; d < 4; d++) {
        const float* fp = g_fragout + (size_t)idxs[d] * 8;
        float4 a = *(const float4*)fp;
        float4 b = *(const float4*)(fp + 4);
        acc0.x += a.x; acc0.y += a.y; acc0.z += a.z; acc0.w += a.w;
        acc1.x += b.x; acc1.y += b.y; acc1.z += b.z; acc1.w += b.w;
    }
    *(float4*)(out + (size_t)n * 8)     = acc0;
    *(float4*)(out + (size_t)n * 8 + 4) = acc1;
}

// ============================================================
extern "C" void kernel_launch(void* const* d_in, const int* in_sizes, int n_in,
                              void* d_out, int out_size)
{
    const float* feature = (const float*)d_in[0];
    const float* WgL     = (const float*)d_in[1];
    const float* WgR     = (const float*)d_in[2];
    const float* W_ih    = (const float*)d_in[3];
    const float* W_hh    = (const float*)d_in[4];
    const float* b_ih    = (const float*)d_in[5];
    const float* b_hh    = (const float*)d_in[6];
    const float* Wg_frag = (const float*)d_in[7];
    const float* W_out   = (const float*)d_in[8];
    const float* b_out   = (const float*)d_in[9];
    const int* lost      = (const int*)d_in[10];
    const int* ret       = (const int*)d_in[11];
    const int* join      = (const int*)d_in[12];
    const int* comb      = (const int*)d_in[13];
    float* out = (float*)d_out;

    const int DSM = 73728;   // 6 x (8KB A + 4KB B)
    cudaFuncSetAttribute(gemm_fused<0>, cudaFuncAttributeMaxDynamicSharedMemorySize, DSM);
    cudaFuncSetAttribute(gemm_fused<1>, cudaFuncAttributeMaxDynamicSharedMemorySize, DSM);
    cudaFuncSetAttribute(gemm_fused<2>, cudaFuncAttributeMaxDynamicSharedMemorySize, DSM);

    // K0: merged prep (feature table + quad weights + step0 weights)
    conv_all<<<37500 + 3072 + 1536, 256>>>(feature, W_ih, W_hh, b_ih, b_hh);

    // K1: cleavage attention
    cleav_kernel<<<N_CLEAV / 8, 256>>>(WgL, WgR, lost, ret);

    // GEMM-A1: (i,g) gates -> c1   (N=512, K=512)
    gemm_fused<0><<<dim3(8, N_FRAG / 128), 256, DSM>>>(join);

    // GEMM-A2: o gates -> h1h      (N=256, K=512)
    gemm_fused<1><<<dim3(4, N_FRAG / 128), 256, DSM>>>(join);

    // GEMM-B: step1 -> h2h         (N=1024, K=768)
    gemm_fused<2><<<dim3(16, N_FRAG / 128), 256, DSM>>>(join);

    // K5: attention + output head
    attn_out<<<N_FRAG / 8, 256>>>(Wg_frag, W_out, b_out);

    // K6: combine scatter-sum
    combine_kernel<<<(N_OUTN + 255) / 256, 256>>>(comb, out);
}